// round 3
// baseline (speedup 1.0000x reference)
#include <cuda_runtime.h>

#define B   8
#define EH  768
#define T   512
#define PH  320
#define U   128
#define JH  320
#define C   34

// Scratch (device globals; no runtime allocation allowed)
__device__ float  g_Wt [EH * JH];            // W_enc transposed: [k][j]
__device__ float  g_Wpt[PH * JH];            // W_pred transposed: [k][j]
__device__ float  g_e  [B * T * JH];         // e[b][t][j]
__device__ float4 g_p4 [B * (JH / 4) * U];   // p interleaved: [b][j/4][u] -> (j%4 in .x...w)

// ---------------------------------------------------------------------------
// K0: transpose weights so the GEMM kernels read k-major (coalesced over j)
// ---------------------------------------------------------------------------
__global__ void k_transpose(const float* __restrict__ W_enc,
                            const float* __restrict__ W_pred) {
    int i = blockIdx.x * blockDim.x + threadIdx.x;
    if (i < EH * JH) {
        int k = i / JH, j = i % JH;
        g_Wt[i] = W_enc[j * EH + k];
    }
    if (i < PH * JH) {
        int k = i / JH, j = i % JH;
        g_Wpt[i] = W_pred[j * PH + k];
    }
}

// ---------------------------------------------------------------------------
// K1: e[b][t][j] = sum_k enc[b][k][t] * W_enc[j][k] + b_enc[j]
// One CTA = (b, 16 consecutive t).  320 threads, thread = j.
// enc slab staged in smem (768x16 fp32 = 48 KB exactly).
// ---------------------------------------------------------------------------
__global__ __launch_bounds__(320) void k_enc(const float* __restrict__ enc,
                                             const float* __restrict__ b_enc) {
    __shared__ float enc_s[EH * 16];   // [k][t] (48 KB)
    const int b  = blockIdx.x >> 5;          // 32 tiles of 16 t per batch
    const int t0 = (blockIdx.x & 31) << 4;
    const int tid = threadIdx.x;

    const float* src = enc + (size_t)b * EH * T + t0;
    for (int i = tid; i < EH * 16; i += 320) {
        int k = i >> 4, t = i & 15;
        enc_s[i] = src[k * T + t];
    }
    __syncthreads();

    const int j = tid;
    float acc[16];
    {
        float bj = b_enc[j];
#pragma unroll
        for (int t = 0; t < 16; t++) acc[t] = bj;
    }

#pragma unroll 1
    for (int k = 0; k < EH; k += 4) {
#pragma unroll
        for (int kk = 0; kk < 4; kk++) {
            float w = g_Wt[(k + kk) * JH + j];
            const float4* ev = (const float4*)&enc_s[(k + kk) * 16];
            float4 e0 = ev[0], e1 = ev[1], e2 = ev[2], e3 = ev[3];
            acc[0]  += w * e0.x;  acc[1]  += w * e0.y;
            acc[2]  += w * e0.z;  acc[3]  += w * e0.w;
            acc[4]  += w * e1.x;  acc[5]  += w * e1.y;
            acc[6]  += w * e1.z;  acc[7]  += w * e1.w;
            acc[8]  += w * e2.x;  acc[9]  += w * e2.y;
            acc[10] += w * e2.z;  acc[11] += w * e2.w;
            acc[12] += w * e3.x;  acc[13] += w * e3.y;
            acc[14] += w * e3.z;  acc[15] += w * e3.w;
        }
    }

    float* dst = g_e + ((size_t)b * T + t0) * JH + j;
#pragma unroll
    for (int t = 0; t < 16; t++) dst[t * JH] = acc[t];
}

// ---------------------------------------------------------------------------
// K2: p[b][u][j] = sum_k dec[b][k][u] * W_pred[j][k] + b_pred[j]
// One CTA = (b, 8 consecutive u).  320 threads, thread = j.
// Stores interleaved float4 layout g_p4[b][j/4][u] for coalesced main-kernel loads.
// ---------------------------------------------------------------------------
__global__ __launch_bounds__(320) void k_pred(const float* __restrict__ dec,
                                              const float* __restrict__ b_pred) {
    __shared__ float dec_s[PH * 8];    // [k][u] (10 KB)
    const int b  = blockIdx.x >> 4;          // 16 tiles of 8 u per batch
    const int u0 = (blockIdx.x & 15) << 3;
    const int tid = threadIdx.x;

    const float* src = dec + (size_t)b * PH * U + u0;
    for (int i = tid; i < PH * 8; i += 320) {
        int k = i >> 3, uu = i & 7;
        dec_s[i] = src[k * U + uu];
    }
    __syncthreads();

    const int j = tid;
    float acc[8];
    {
        float bj = b_pred[j];
#pragma unroll
        for (int uu = 0; uu < 8; uu++) acc[uu] = bj;
    }

#pragma unroll 1
    for (int k = 0; k < PH; k += 4) {
#pragma unroll
        for (int kk = 0; kk < 4; kk++) {
            float w = g_Wpt[(k + kk) * JH + j];
            const float4* dv = (const float4*)&dec_s[(k + kk) * 8];
            float4 d0 = dv[0], d1 = dv[1];
            acc[0] += w * d0.x;  acc[1] += w * d0.y;
            acc[2] += w * d0.z;  acc[3] += w * d0.w;
            acc[4] += w * d1.x;  acc[5] += w * d1.y;
            acc[6] += w * d1.z;  acc[7] += w * d1.w;
        }
    }

    float* p4f = (float*)g_p4;
    const int base = ((b * (JH / 4) + (j >> 2)) * U) * 4 + (j & 3);
#pragma unroll
    for (int uu = 0; uu < 8; uu++) p4f[base + (u0 + uu) * 4] = acc[uu];
}

// ---------------------------------------------------------------------------
// K3 (main, fused): for each (b,t,u):
//   h_j = relu(e[b][t][j] + p[b][u][j]),  logits_c = sum_j h_j * W_out[c][j] + b_out[c]
//   out = log_softmax(logits)
// One CTA = one (b,t); 128 threads = 128 u.  W_out + e-row in smem (broadcast).
// ---------------------------------------------------------------------------
__global__ __launch_bounds__(128) void k_main(const float* __restrict__ W_out,
                                              const float* __restrict__ b_out,
                                              float* __restrict__ out) {
    __shared__ float W_s[C * JH];   // 34*320*4 = 43.5 KB, [c][j]
    __shared__ float e_s[JH];
    const int bx = blockIdx.x;
    const int b = bx >> 9;          // T = 512
    const int t = bx & 511;
    const int tid = threadIdx.x;

    for (int i = tid; i < C * JH; i += 128) W_s[i] = W_out[i];
    {
        const float* erow = g_e + ((size_t)b * T + t) * JH;
        for (int i = tid; i < JH; i += 128) e_s[i] = erow[i];
    }
    __syncthreads();

    const int u = tid;
    float acc[C];
#pragma unroll
    for (int c = 0; c < C; c++) acc[c] = b_out[c];

    const float4* prow = g_p4 + (size_t)b * (JH / 4) * U + u;

#pragma unroll 1
    for (int jc = 0; jc < JH / 8; jc++) {
        float4 pa = prow[(2 * jc) * U];
        float4 pb = prow[(2 * jc + 1) * U];
        float4 ea = *(const float4*)&e_s[jc * 8];
        float4 eb = *(const float4*)&e_s[jc * 8 + 4];

        float h0 = fmaxf(ea.x + pa.x, 0.f);
        float h1 = fmaxf(ea.y + pa.y, 0.f);
        float h2 = fmaxf(ea.z + pa.z, 0.f);
        float h3 = fmaxf(ea.w + pa.w, 0.f);
        float h4 = fmaxf(eb.x + pb.x, 0.f);
        float h5 = fmaxf(eb.y + pb.y, 0.f);
        float h6 = fmaxf(eb.z + pb.z, 0.f);
        float h7 = fmaxf(eb.w + pb.w, 0.f);

#pragma unroll
        for (int c = 0; c < C; c++) {
            const float4* wr = (const float4*)&W_s[c * JH + jc * 8];
            float4 w0 = wr[0], w1 = wr[1];
            acc[c] += h0 * w0.x + h1 * w0.y + h2 * w0.z + h3 * w0.w
                    + h4 * w1.x + h5 * w1.y + h6 * w1.z + h7 * w1.w;
        }
    }

    // log_softmax over C
    float m = acc[0];
#pragma unroll
    for (int c = 1; c < C; c++) m = fmaxf(m, acc[c]);
    float s = 0.f;
#pragma unroll
    for (int c = 0; c < C; c++) s += expf(acc[c] - m);
    float lse = m + logf(s);

    float* o = out + (((size_t)(b * T + t)) * U + u) * C;
#pragma unroll
    for (int c = 0; c < C; c++) o[c] = acc[c] - lse;
}

// ---------------------------------------------------------------------------
extern "C" void kernel_launch(void* const* d_in, const int* in_sizes, int n_in,
                              void* d_out, int out_size) {
    const float* enc    = (const float*)d_in[0];
    const float* dec    = (const float*)d_in[1];
    const float* W_enc  = (const float*)d_in[2];
    const float* b_enc  = (const float*)d_in[3];
    const float* W_pred = (const float*)d_in[4];
    const float* b_pred = (const float*)d_in[5];
    const float* W_out  = (const float*)d_in[6];
    const float* b_out  = (const float*)d_in[7];
    float* out = (float*)d_out;

    k_transpose<<<(EH * JH + 255) / 256, 256>>>(W_enc, W_pred);
    k_enc <<<B * (T / 16), 320>>>(enc, b_enc);
    k_pred<<<B * (U / 8),  320>>>(dec, b_pred);
    k_main<<<B * T, 128>>>(W_out, b_out, out);
}

// round 4
// speedup vs baseline: 1.0933x; 1.0933x over previous
#include <cuda_runtime.h>

#define B   8
#define EH  768
#define T   512
#define PH  320
#define U   128
#define JH  320
#define C   34

typedef unsigned long long u64;

// Scratch (device globals; no runtime allocation allowed)
__device__ float  g_Wt [EH * JH];            // W_enc transposed: [k][j]
__device__ float  g_Wpt[PH * JH];            // W_pred transposed: [k][j]
__device__ float  g_e  [B * T * JH];         // e[b][t][j]
__device__ float4 g_p4 [B * (JH / 4) * U];   // p interleaved: [b][j/4][u] -> (j%4 in .x..w)

// ---- f32x2 packed helpers -------------------------------------------------
__device__ __forceinline__ u64 pack2(float lo, float hi) {
    u64 r;
    asm("mov.b64 %0, {%1, %2};" : "=l"(r) : "f"(lo), "f"(hi));
    return r;
}
__device__ __forceinline__ void unpack2(u64 v, float& lo, float& hi) {
    asm("mov.b64 {%0, %1}, %2;" : "=f"(lo), "=f"(hi) : "l"(v));
}
// acc += a * b  (elementwise on packed f32x2)
#define FMA2(acc, a, b) \
    asm("fma.rn.f32x2 %0, %1, %2, %0;" : "+l"(acc) : "l"(a), "l"(b))

// 16B shared load returning two packed f32x2 (LDS.128)
__device__ __forceinline__ void lds_2x64(u64& a, u64& b, const float* p) {
    unsigned sa = (unsigned)__cvta_generic_to_shared(p);
    asm("ld.shared.v2.u64 {%0, %1}, [%2];" : "=l"(a), "=l"(b) : "r"(sa));
}

// ---------------------------------------------------------------------------
// K0: transpose weights so the GEMM kernels read k-major (coalesced over j)
// ---------------------------------------------------------------------------
__global__ void k_transpose(const float* __restrict__ W_enc,
                            const float* __restrict__ W_pred) {
    int i = blockIdx.x * blockDim.x + threadIdx.x;
    if (i < EH * JH) {
        int k = i / JH, j = i % JH;
        g_Wt[i] = W_enc[j * EH + k];
    }
    if (i < PH * JH) {
        int k = i / JH, j = i % JH;
        g_Wpt[i] = W_pred[j * PH + k];
    }
}

// ---------------------------------------------------------------------------
// K1: e[b][t][j] = sum_k enc[b][k][t] * W_enc[j][k] + b_enc[j]
// One CTA = (b, 16 consecutive t).  320 threads, thread = j.
// Packed f32x2 over t-pairs: acc[m] = {t=2m, t=2m+1}.
// ---------------------------------------------------------------------------
__global__ __launch_bounds__(320) void k_enc(const float* __restrict__ enc,
                                             const float* __restrict__ b_enc) {
    __shared__ float enc_s[EH * 16];   // [k][t] (48 KB)
    const int b  = blockIdx.x >> 5;
    const int t0 = (blockIdx.x & 31) << 4;
    const int tid = threadIdx.x;

    const float* src = enc + (size_t)b * EH * T + t0;
    for (int i = tid; i < EH * 16; i += 320) {
        int k = i >> 4, t = i & 15;
        enc_s[i] = src[k * T + t];
    }
    __syncthreads();

    const int j = tid;
    u64 acc[8];
    {
        float bj = b_enc[j];
        u64 bj2 = pack2(bj, bj);
#pragma unroll
        for (int m = 0; m < 8; m++) acc[m] = bj2;
    }

#pragma unroll 1
    for (int k = 0; k < EH; k += 4) {
#pragma unroll
        for (int kk = 0; kk < 4; kk++) {
            float w = g_Wt[(k + kk) * JH + j];
            u64 wp = pack2(w, w);
            const float* er = &enc_s[(k + kk) * 16];
            u64 e0, e1, e2, e3, e4, e5, e6, e7;
            lds_2x64(e0, e1, er);
            lds_2x64(e2, e3, er + 4);
            lds_2x64(e4, e5, er + 8);
            lds_2x64(e6, e7, er + 12);
            FMA2(acc[0], wp, e0);  FMA2(acc[1], wp, e1);
            FMA2(acc[2], wp, e2);  FMA2(acc[3], wp, e3);
            FMA2(acc[4], wp, e4);  FMA2(acc[5], wp, e5);
            FMA2(acc[6], wp, e6);  FMA2(acc[7], wp, e7);
        }
    }

    float* dst = g_e + ((size_t)b * T + t0) * JH + j;
#pragma unroll
    for (int m = 0; m < 8; m++) {
        float lo, hi;
        unpack2(acc[m], lo, hi);
        dst[(2 * m) * JH]     = lo;
        dst[(2 * m + 1) * JH] = hi;
    }
}

// ---------------------------------------------------------------------------
// K2: p[b][u][j] = sum_k dec[b][k][u] * W_pred[j][k] + b_pred[j]
// One CTA = (b, 8 consecutive u).  320 threads, thread = j. Packed over u-pairs.
// ---------------------------------------------------------------------------
__global__ __launch_bounds__(320) void k_pred(const float* __restrict__ dec,
                                              const float* __restrict__ b_pred) {
    __shared__ float dec_s[PH * 8];    // [k][u] (10 KB)
    const int b  = blockIdx.x >> 4;
    const int u0 = (blockIdx.x & 15) << 3;
    const int tid = threadIdx.x;

    const float* src = dec + (size_t)b * PH * U + u0;
    for (int i = tid; i < PH * 8; i += 320) {
        int k = i >> 3, uu = i & 7;
        dec_s[i] = src[k * U + uu];
    }
    __syncthreads();

    const int j = tid;
    u64 acc[4];
    {
        float bj = b_pred[j];
        u64 bj2 = pack2(bj, bj);
#pragma unroll
        for (int m = 0; m < 4; m++) acc[m] = bj2;
    }

#pragma unroll 1
    for (int k = 0; k < PH; k += 4) {
#pragma unroll
        for (int kk = 0; kk < 4; kk++) {
            float w = g_Wpt[(k + kk) * JH + j];
            u64 wp = pack2(w, w);
            const float* dr = &dec_s[(k + kk) * 8];
            u64 d0, d1, d2, d3;
            lds_2x64(d0, d1, dr);
            lds_2x64(d2, d3, dr + 4);
            FMA2(acc[0], wp, d0);  FMA2(acc[1], wp, d1);
            FMA2(acc[2], wp, d2);  FMA2(acc[3], wp, d3);
        }
    }

    float* p4f = (float*)g_p4;
    const int base = ((b * (JH / 4) + (j >> 2)) * U) * 4 + (j & 3);
#pragma unroll
    for (int m = 0; m < 4; m++) {
        float lo, hi;
        unpack2(acc[m], lo, hi);
        p4f[base + (u0 + 2 * m) * 4]     = lo;
        p4f[base + (u0 + 2 * m + 1) * 4] = hi;
    }
}

// ---------------------------------------------------------------------------
// K3 (main, fused): one CTA = (b, {t0, t0+1}); 128 threads = u.
// Per (t,u): h_j = relu(e+p); logits_c = sum_j h_j W_out[c][j]; log_softmax.
// Packed f32x2 over j-pairs; W_out smem reads + p global reads amortized
// over the two t values.
// ---------------------------------------------------------------------------
__global__ __launch_bounds__(128) void k_main(const float* __restrict__ W_out,
                                              const float* __restrict__ b_out,
                                              float* __restrict__ out) {
    __shared__ float W_s[C * JH];    // 43.5 KB, [c][j]
    __shared__ float e_s[2 * JH];    // two t rows
    const int bx = blockIdx.x;
    const int b  = bx >> 8;          // T/2 = 256 tiles per batch
    const int t0 = (bx & 255) << 1;
    const int tid = threadIdx.x;

    for (int i = tid; i < C * JH; i += 128) W_s[i] = W_out[i];
    {
        const float* erow = g_e + ((size_t)b * T + t0) * JH;
        for (int i = tid; i < 2 * JH; i += 128) e_s[i] = erow[i];
    }
    __syncthreads();

    const int u = tid;
    u64 accA[C];   // t0   : {even-j, odd-j} partials
    u64 accB[C];   // t0+1
#pragma unroll
    for (int c = 0; c < C; c++) { accA[c] = 0ull; accB[c] = 0ull; }

    const float4* prow = g_p4 + (size_t)b * (JH / 4) * U + u;

#pragma unroll 1
    for (int jc = 0; jc < JH / 8; jc++) {
        float4 pa = prow[(2 * jc) * U];
        float4 pb = prow[(2 * jc + 1) * U];
        float4 ea0 = *(const float4*)&e_s[jc * 8];
        float4 eb0 = *(const float4*)&e_s[jc * 8 + 4];
        float4 ea1 = *(const float4*)&e_s[JH + jc * 8];
        float4 eb1 = *(const float4*)&e_s[JH + jc * 8 + 4];

        // h for t0, packed into j-pairs
        u64 hA0 = pack2(fmaxf(ea0.x + pa.x, 0.f), fmaxf(ea0.y + pa.y, 0.f));
        u64 hA1 = pack2(fmaxf(ea0.z + pa.z, 0.f), fmaxf(ea0.w + pa.w, 0.f));
        u64 hA2 = pack2(fmaxf(eb0.x + pb.x, 0.f), fmaxf(eb0.y + pb.y, 0.f));
        u64 hA3 = pack2(fmaxf(eb0.z + pb.z, 0.f), fmaxf(eb0.w + pb.w, 0.f));
        // h for t0+1
        u64 hB0 = pack2(fmaxf(ea1.x + pa.x, 0.f), fmaxf(ea1.y + pa.y, 0.f));
        u64 hB1 = pack2(fmaxf(ea1.z + pa.z, 0.f), fmaxf(ea1.w + pa.w, 0.f));
        u64 hB2 = pack2(fmaxf(eb1.x + pb.x, 0.f), fmaxf(eb1.y + pb.y, 0.f));
        u64 hB3 = pack2(fmaxf(eb1.z + pb.z, 0.f), fmaxf(eb1.w + pb.w, 0.f));

#pragma unroll
        for (int c = 0; c < C; c++) {
            const float* wr = &W_s[c * JH + jc * 8];
            u64 w01, w23, w45, w67;
            lds_2x64(w01, w23, wr);
            lds_2x64(w45, w67, wr + 4);
            FMA2(accA[c], hA0, w01);  FMA2(accA[c], hA1, w23);
            FMA2(accA[c], hA2, w45);  FMA2(accA[c], hA3, w67);
            FMA2(accB[c], hB0, w01);  FMA2(accB[c], hB1, w23);
            FMA2(accB[c], hB2, w45);  FMA2(accB[c], hB3, w67);
        }
    }

    // epilogue: per-t horizontal sum + bias + log_softmax + store
#pragma unroll 1
    for (int tt = 0; tt < 2; tt++) {
        float logits[C];
#pragma unroll
        for (int c = 0; c < C; c++) {
            float lo, hi;
            unpack2(tt == 0 ? accA[c] : accB[c], lo, hi);
            logits[c] = lo + hi + b_out[c];
        }
        float m = logits[0];
#pragma unroll
        for (int c = 1; c < C; c++) m = fmaxf(m, logits[c]);
        float s = 0.f;
#pragma unroll
        for (int c = 0; c < C; c++) s += expf(logits[c] - m);
        float lse = m + logf(s);

        float* o = out + (((size_t)(b * T + t0 + tt)) * U + u) * C;
#pragma unroll
        for (int c = 0; c < C; c++) o[c] = logits[c] - lse;
    }
}

// ---------------------------------------------------------------------------
extern "C" void kernel_launch(void* const* d_in, const int* in_sizes, int n_in,
                              void* d_out, int out_size) {
    const float* enc    = (const float*)d_in[0];
    const float* dec    = (const float*)d_in[1];
    const float* W_enc  = (const float*)d_in[2];
    const float* b_enc  = (const float*)d_in[3];
    const float* W_pred = (const float*)d_in[4];
    const float* b_pred = (const float*)d_in[5];
    const float* W_out  = (const float*)d_in[6];
    const float* b_out  = (const float*)d_in[7];
    float* out = (float*)d_out;

    k_transpose<<<(EH * JH + 255) / 256, 256>>>(W_enc, W_pred);
    k_enc <<<B * (T / 16), 320>>>(enc, b_enc);
    k_pred<<<B * (U / 8),  320>>>(dec, b_pred);
    k_main<<<B * (T / 2), 128>>>(W_out, b_out, out);
}